// round 16
// baseline (speedup 1.0000x reference)
#include <cuda_runtime.h>
#include <cuda_fp16.h>
#include <cuda_bf16.h>

// Problem constants
#define BB   4
#define CC   256
#define HH   128
#define WW   128
#define KK   1000
#define POOLED 7
#define NBIN (POOLED*POOLED)          // 49
#define PER_ROI (CC*NBIN)             // 12544 floats per ROI
#define HWSZ (HH*WW)
#define PSTR 261                      // smem staging row stride (odd -> conflict-free reads)

// 32 MB fp16 NHWC scratch (device global: the sanctioned no-alloc workaround)
__device__ __half g_tfeat[BB * HH * WW * CC];

static __device__ __forceinline__ __half2 u2h(unsigned int u) {
    __half2 h; *(unsigned int*)&h = u; return h;
}
static __device__ __forceinline__ unsigned int h2u(__half2 h) {
    return *(unsigned int*)&h;
}

// ---------------------------------------------------------------------------
// Kernel 1: NCHW fp32 -> NHWC fp16 transpose, 4 y-rows per CTA.
// ---------------------------------------------------------------------------
__global__ void nchw_to_nhwc(const float* __restrict__ f) {
    __shared__ float tile[4][32][33];
    const int i  = threadIdx.x;
    const int x0 = blockIdx.x * 32;
    const int c0 = blockIdx.y * 32;
    const int bz = blockIdx.z;          // 0 .. BB*HH/4-1
    const int b  = bz >> 5;
    const int y0 = (bz & 31) * 4;

    {   // Phase 1: 4 independent coalesced float4 reads
        const int cl = i >> 3;
        const int xq = i & 7;
        const float* src = f + (((size_t)(b * CC + c0 + cl) * HH + y0) * WW + x0 + 4 * xq);
#pragma unroll
        for (int t = 0; t < 4; ++t) {
            const float4 v = *(const float4*)(src + t * WW);
            tile[t][cl][4 * xq + 0] = v.x;
            tile[t][cl][4 * xq + 1] = v.y;
            tile[t][cl][4 * xq + 2] = v.z;
            tile[t][cl][4 * xq + 3] = v.w;
        }
    }
    __syncthreads();
    {   // Phase 2: 4 independent coalesced 8B half-quad writes
        const int xl = i >> 3;
        const int cq = i & 7;
        __half* dst = g_tfeat + (((size_t)(b * HH + y0) * WW + x0 + xl) * CC + c0 + 4 * cq);
#pragma unroll
        for (int t = 0; t < 4; ++t) {
            const __half2 lo = __floats2half2_rn(tile[t][4 * cq + 0][xl],
                                                 tile[t][4 * cq + 1][xl]);
            const __half2 hi = __floats2half2_rn(tile[t][4 * cq + 2][xl],
                                                 tile[t][4 * cq + 3][xl]);
            uint2 pk;
            pk.x = h2u(lo);
            pk.y = h2u(hi);
            *(uint2*)(dst + (size_t)t * (WW * CC)) = pk;
        }
    }
}

// ---------------------------------------------------------------------------
// Kernel 2: fused ROI align. One CTA per ROI, 256 threads = 8 bin-groups x
// 32 channel-OCT lanes (LDG.128 taps). HFMA2 combine with the chain carried
// across the GW x-samples (one fp32 convert per iy-row); 1/(gh*gw) folded
// into the packed weights. Interleaved smem staging, coalesced write-out.
// ---------------------------------------------------------------------------
template<int GH, int GW>
__device__ __forceinline__ void process_bin(
    int bin, int c, const __half* __restrict__ base,
    const int* __restrict__ sxl, const int* __restrict__ sxh,
    const int* __restrict__ syl, const int* __restrict__ syh,
    const uint4* __restrict__ swq,
    float* __restrict__ so)
{
    const int py = bin / POOLED;
    const int px = bin - py * POOLED;
    float a0 = 0.f, a1 = 0.f, a2 = 0.f, a3 = 0.f;
    float a4 = 0.f, a5 = 0.f, a6 = 0.f, a7 = 0.f;
#pragma unroll
    for (int iy = 0; iy < GH; ++iy) {
        const int ys = py * 2 + iy;
        const __half* rl = base + syl[ys];    // pre-scaled y*W*C
        const __half* rh = base + syh[ys];
        __half2 s0, s1, s2, s3;
#pragma unroll
        for (int jx = 0; jx < GW; ++jx) {
            const int xs = px * 2 + jx;
            const int xl = sxl[xs];           // pre-scaled x*C
            const int xh = sxh[xs];
            const uint4 wq = swq[ys * 14 + xs];   // packed half2 weights (invn folded)
            const __half2 w00 = u2h(wq.x);
            const __half2 w01 = u2h(wq.y);
            const __half2 w10 = u2h(wq.z);
            const __half2 w11 = u2h(wq.w);
            const uint4 r00 = __ldg((const uint4*)(rl + xl));
            const uint4 r01 = __ldg((const uint4*)(rl + xh));
            const uint4 r10 = __ldg((const uint4*)(rh + xl));
            const uint4 r11 = __ldg((const uint4*)(rh + xh));
            if (jx == 0) {
                s0 = __hmul2(w00, u2h(r00.x));
                s1 = __hmul2(w00, u2h(r00.y));
                s2 = __hmul2(w00, u2h(r00.z));
                s3 = __hmul2(w00, u2h(r00.w));
            } else {
                s0 = __hfma2(w00, u2h(r00.x), s0);
                s1 = __hfma2(w00, u2h(r00.y), s1);
                s2 = __hfma2(w00, u2h(r00.z), s2);
                s3 = __hfma2(w00, u2h(r00.w), s3);
            }
            s0 = __hfma2(w01, u2h(r01.x), s0);
            s1 = __hfma2(w01, u2h(r01.y), s1);
            s2 = __hfma2(w01, u2h(r01.z), s2);
            s3 = __hfma2(w01, u2h(r01.w), s3);
            s0 = __hfma2(w10, u2h(r10.x), s0);
            s1 = __hfma2(w10, u2h(r10.y), s1);
            s2 = __hfma2(w10, u2h(r10.z), s2);
            s3 = __hfma2(w10, u2h(r10.w), s3);
            s0 = __hfma2(w11, u2h(r11.x), s0);
            s1 = __hfma2(w11, u2h(r11.y), s1);
            s2 = __hfma2(w11, u2h(r11.z), s2);
            s3 = __hfma2(w11, u2h(r11.w), s3);
        }
        // One fp32 convert+accumulate per iy-row
        const float2 f0 = __half22float2(s0);
        const float2 f1 = __half22float2(s1);
        const float2 f2 = __half22float2(s2);
        const float2 f3 = __half22float2(s3);
        a0 += f0.x; a1 += f0.y; a2 += f1.x; a3 += f1.y;
        a4 += f2.x; a5 += f2.y; a6 += f3.x; a7 += f3.y;
    }
    // Interleaved staging: channel (8c+j) -> so[bin*PSTR + c + 32*j]
    float* dst = so + bin * PSTR + c;
    dst[0 * 32] = a0;
    dst[1 * 32] = a1;
    dst[2 * 32] = a2;
    dst[3 * 32] = a3;
    dst[4 * 32] = a4;
    dst[5 * 32] = a5;
    dst[6 * 32] = a6;
    dst[7 * 32] = a7;
}

template<int GH, int GW>
__device__ __forceinline__ void roi_body(
    int g, int c, const __half* __restrict__ base,
    const int* __restrict__ sxl, const int* __restrict__ sxh,
    const int* __restrict__ syl, const int* __restrict__ syh,
    const uint4* __restrict__ swq,
    float* __restrict__ so)
{
    const int start = 6 * g;
#pragma unroll
    for (int j = 0; j < 6; ++j) {
        process_bin<GH, GW>(start + j, c, base, sxl, sxh, syl, syh, swq, so);
    }
    if (g == 7) {   // leftover bin 48 (warp-uniform; table-build warps excluded)
        process_bin<GH, GW>(48, c, base, sxl, sxh, syl, syh, swq, so);
    }
}

__global__ void __launch_bounds__(256, 4)
roi_align_kernel(const float* __restrict__ boxes, float* __restrict__ out) {
    extern __shared__ float so[];            // NBIN*PSTR floats = 51156 B
    __shared__ int   sxl[14], sxh[14], syl[14], syh[14];
    __shared__ float slx[14], shx[14], sly[14], shy[14];
    __shared__ uint4 swq[196];               // packed half2 weight quads (invn folded)
    __shared__ float sinvn;

    const int k   = blockIdx.x;
    const int tid = threadIdx.x;
    const int g   = tid >> 5;      // bin group (warp)
    const int c   = tid & 31;      // channel oct

    // Phase A: per-axis sample tables with pre-scaled offsets
    if (tid < 28) {
        const float x1 = __ldg(boxes + k * 5 + 1) * 0.25f;
        const float y1 = __ldg(boxes + k * 5 + 2) * 0.25f;
        const float x2 = __ldg(boxes + k * 5 + 3) * 0.25f;
        const float y2 = __ldg(boxes + k * 5 + 4) * 0.25f;
        const float roi_w = fmaxf(x2 - x1, 1.0f);
        const float roi_h = fmaxf(y2 - y1, 1.0f);

        if (tid == 0) {
            const float ghf = ceilf(roi_h * (1.0f / POOLED));
            const float gwf = ceilf(roi_w * (1.0f / POOLED));
            sinvn = 1.0f / (ghf * gwf);
        }

        const bool isy = tid >= 14;
        const int  s   = isy ? tid - 14 : tid;
        const int  p   = s >> 1;
        const int  i   = s & 1;
        const float start = isy ? y1 : x1;
        const float rs    = isy ? roi_h : roi_w;
        const float bs    = rs * (1.0f / POOLED);
        const int   gq    = (int)ceilf(rs * (1.0f / POOLED));
        const float coord = start + (float)p * bs + ((float)i + 0.5f) * bs / (float)gq;

        const bool valid = (coord >= -1.0f) && (coord <= 128.0f);
        float cc = fmaxf(coord, 0.0f);
        int lo = min((int)cc, 127);
        int hi = min(lo + 1, 127);
        float l = (lo >= 127) ? 0.0f : (cc - (float)lo);
        float h = 1.0f - l;
        if (!valid) { l = 0.0f; h = 0.0f; }   // zero both factors -> sample = 0
        if (isy) { syl[s] = lo * (WW * CC); syh[s] = hi * (WW * CC); sly[s] = l; shy[s] = h; }
        else     { sxl[s] = lo * CC;        sxh[s] = hi * CC;        slx[s] = l; shx[s] = h; }
    }
    __syncthreads();

    // Phase B: packed per-sample weight quads with 1/(gh*gw) folded in
    if (tid < 196) {
        const int ys = tid / 14;
        const int xs = tid - ys * 14;
        const float nn = sinvn;
        const float hy = shy[ys] * nn, ly = sly[ys] * nn;
        const float hx = shx[xs],      lx = slx[xs];
        uint4 q;
        q.x = h2u(__float2half2_rn(hy * hx));
        q.y = h2u(__float2half2_rn(hy * lx));
        q.z = h2u(__float2half2_rn(ly * hx));
        q.w = h2u(__float2half2_rn(ly * lx));
        swq[tid] = q;
    }
    __syncthreads();

    const int b = (int)__ldg(boxes + k * 5 + 0);
    const float roi_w = fmaxf((__ldg(boxes + k*5+3) - __ldg(boxes + k*5+1)) * 0.25f, 1.0f);
    const float roi_h = fmaxf((__ldg(boxes + k*5+4) - __ldg(boxes + k*5+2)) * 0.25f, 1.0f);
    const int gw2 = min((int)ceilf(roi_w * (1.0f / POOLED)), 2);
    const int gh2 = min((int)ceilf(roi_h * (1.0f / POOLED)), 2);

    const __half* base = g_tfeat + (size_t)b * (HWSZ * CC) + 8 * c;

    // CTA-uniform dispatch to fully-unrolled specializations
    if (gh2 == 1) {
        if (gw2 == 1) roi_body<1,1>(g, c, base, sxl, sxh, syl, syh, swq, so);
        else          roi_body<1,2>(g, c, base, sxl, sxh, syl, syh, swq, so);
    } else {
        if (gw2 == 1) roi_body<2,1>(g, c, base, sxl, sxh, syl, syh, swq, so);
        else          roi_body<2,2>(g, c, base, sxl, sxh, syl, syh, swq, so);
    }
    __syncthreads();

    // Coalesced write-out: out[k][ch][bin] = so[bin*PSTR + pos(ch)]
    // pos(ch) = (ch>>3) + ((ch&7)<<5); lanes span bin (odd stride -> no conflicts)
    float* dst = out + (size_t)k * PER_ROI;
#pragma unroll 7
    for (int i = tid; i < PER_ROI; i += 256) {
        const int ch  = i / NBIN;
        const int bin = i - ch * NBIN;
        const int pos = (ch >> 3) + ((ch & 7) << 5);
        dst[i] = so[bin * PSTR + pos];
    }
}

extern "C" void kernel_launch(void* const* d_in, const int* in_sizes, int n_in,
                              void* d_out, int out_size) {
    const float* features = (const float*)d_in[0];   // [4,256,128,128]
    const float* boxes    = (const float*)d_in[1];   // [1000,5]
    float* out = (float*)d_out;                      // [1000,256,7,7]
    (void)in_sizes; (void)n_in; (void)out_size;

    const int smem_bytes = NBIN * PSTR * (int)sizeof(float);
    cudaFuncSetAttribute(roi_align_kernel,
                         cudaFuncAttributeMaxDynamicSharedMemorySize, smem_bytes);

    // 1) NCHW fp32 -> NHWC fp16 scratch (4 y-rows per CTA)
    dim3 gT(WW / 32, CC / 32, BB * HH / 4);
    nchw_to_nhwc<<<gT, 256>>>(features);

    // 2) Fused gather + layout fix-up, one CTA per ROI
    roi_align_kernel<<<KK, 256, smem_bytes>>>(boxes, out);
}

// round 17
// speedup vs baseline: 1.0721x; 1.0721x over previous
#include <cuda_runtime.h>
#include <cuda_fp16.h>
#include <cuda_bf16.h>

// Problem constants
#define BB   4
#define CC   256
#define HH   128
#define WW   128
#define KK   1000
#define POOLED 7
#define NBIN (POOLED*POOLED)          // 49
#define PER_ROI (CC*NBIN)             // 12544 floats per ROI
#define HWSZ (HH*WW)
#define PSTRH 258                     // fp16 staging row stride in halfs (129 words, odd)

// Device scratch (sanctioned no-alloc workaround)
__device__ __half g_tfeat[BB * HH * WW * CC];   // 32 MB fp16 NHWC features
__device__ int    g_perm[KK];                   // LPT-ordered ROI dispatch order

static __device__ __forceinline__ __half2 u2h(unsigned int u) {
    __half2 h; *(unsigned int*)&h = u; return h;
}
static __device__ __forceinline__ unsigned int h2u(__half2 h) {
    return *(unsigned int*)&h;
}

// ---------------------------------------------------------------------------
// Kernel 1: NCHW fp32 -> NHWC fp16 transpose, 4 y-rows per CTA.
// Block (0,0,0) additionally builds the LPT permutation: ROIs bucketed by
// (gh,gw) class, heavy (2x2) first, so the roi kernel's wave-1 gets the
// long CTAs and light ones fill the drain.
// ---------------------------------------------------------------------------
__global__ void nchw_to_nhwc(const float* __restrict__ f,
                             const float* __restrict__ boxes) {
    __shared__ float tile[4][32][33];
    __shared__ int cnt[4];
    __shared__ int basearr[4];
    const int i  = threadIdx.x;

    // --- LPT classification (one CTA only; whole block participates) ---
    if (blockIdx.x == 0 && blockIdx.y == 0 && blockIdx.z == 0) {
        if (i < 4) cnt[i] = 0;
        __syncthreads();
        int myroi[4], mybkt[4], mypos[4];
        int n = 0;
        for (int r = i; r < KK; r += 256) {
            const float roi_w = fmaxf((boxes[r*5+3] - boxes[r*5+1]) * 0.25f, 1.0f);
            const float roi_h = fmaxf((boxes[r*5+4] - boxes[r*5+2]) * 0.25f, 1.0f);
            const int gw2 = min((int)ceilf(roi_w * (1.0f / POOLED)), 2);
            const int gh2 = min((int)ceilf(roi_h * (1.0f / POOLED)), 2);
            const int bkt = (gh2 == 2 && gw2 == 2) ? 0
                          : (gh2 == 2)             ? 1
                          : (gw2 == 2)             ? 2 : 3;
            myroi[n] = r;
            mybkt[n] = bkt;
            mypos[n] = atomicAdd(&cnt[bkt], 1);
            ++n;
        }
        __syncthreads();
        if (i == 0) {
            basearr[0] = 0;
            basearr[1] = cnt[0];
            basearr[2] = cnt[0] + cnt[1];
            basearr[3] = cnt[0] + cnt[1] + cnt[2];
        }
        __syncthreads();
        for (int t = 0; t < n; ++t)
            g_perm[basearr[mybkt[t]] + mypos[t]] = myroi[t];
    }

    const int x0 = blockIdx.x * 32;
    const int c0 = blockIdx.y * 32;
    const int bz = blockIdx.z;          // 0 .. BB*HH/4-1
    const int b  = bz >> 5;
    const int y0 = (bz & 31) * 4;

    {   // Phase 1: 4 independent coalesced float4 reads
        const int cl = i >> 3;
        const int xq = i & 7;
        const float* src = f + (((size_t)(b * CC + c0 + cl) * HH + y0) * WW + x0 + 4 * xq);
#pragma unroll
        for (int t = 0; t < 4; ++t) {
            const float4 v = *(const float4*)(src + t * WW);
            tile[t][cl][4 * xq + 0] = v.x;
            tile[t][cl][4 * xq + 1] = v.y;
            tile[t][cl][4 * xq + 2] = v.z;
            tile[t][cl][4 * xq + 3] = v.w;
        }
    }
    __syncthreads();
    {   // Phase 2: 4 independent coalesced 8B half-quad writes
        const int xl = i >> 3;
        const int cq = i & 7;
        __half* dst = g_tfeat + (((size_t)(b * HH + y0) * WW + x0 + xl) * CC + c0 + 4 * cq);
#pragma unroll
        for (int t = 0; t < 4; ++t) {
            const __half2 lo = __floats2half2_rn(tile[t][4 * cq + 0][xl],
                                                 tile[t][4 * cq + 1][xl]);
            const __half2 hi = __floats2half2_rn(tile[t][4 * cq + 2][xl],
                                                 tile[t][4 * cq + 3][xl]);
            uint2 pk;
            pk.x = h2u(lo);
            pk.y = h2u(hi);
            *(uint2*)(dst + (size_t)t * (WW * CC)) = pk;
        }
    }
}

// ---------------------------------------------------------------------------
// Kernel 2: fused ROI align. One CTA per dispatch slot; ROI id from g_perm.
// 256 threads = 8 bin-groups x 32 channel-OCT lanes (LDG.128 taps), HFMA2
// combine, packed weight quads, per-sample fp32 accumulate (R14 math).
// Staging is fp16 (25.3 KB) -> 5 CTAs/SM and ~100 KB L1D for tap reuse.
// ---------------------------------------------------------------------------
template<int GH, int GW>
__device__ __forceinline__ void process_bin(
    int bin, int c, const __half* __restrict__ base, float invn,
    const int* __restrict__ sxl, const int* __restrict__ sxh,
    const int* __restrict__ syl, const int* __restrict__ syh,
    const uint4* __restrict__ swq,
    __half* __restrict__ so_h)
{
    const int py = bin / POOLED;
    const int px = bin - py * POOLED;
    float a0 = 0.f, a1 = 0.f, a2 = 0.f, a3 = 0.f;
    float a4 = 0.f, a5 = 0.f, a6 = 0.f, a7 = 0.f;
#pragma unroll
    for (int iy = 0; iy < GH; ++iy) {
        const int ys = py * 2 + iy;
        const __half* rl = base + syl[ys];    // pre-scaled y*W*C
        const __half* rh = base + syh[ys];
#pragma unroll
        for (int jx = 0; jx < GW; ++jx) {
            const int xs = px * 2 + jx;
            const int xl = sxl[xs];           // pre-scaled x*C
            const int xh = sxh[xs];
            const uint4 wq = swq[ys * 14 + xs];   // packed half2 weights
            const __half2 w00 = u2h(wq.x);
            const __half2 w01 = u2h(wq.y);
            const __half2 w10 = u2h(wq.z);
            const __half2 w11 = u2h(wq.w);
            const uint4 r00 = __ldg((const uint4*)(rl + xl));
            const uint4 r01 = __ldg((const uint4*)(rl + xh));
            const uint4 r10 = __ldg((const uint4*)(rh + xl));
            const uint4 r11 = __ldg((const uint4*)(rh + xh));
            __half2 s0 = __hmul2(w00, u2h(r00.x));
            __half2 s1 = __hmul2(w00, u2h(r00.y));
            __half2 s2 = __hmul2(w00, u2h(r00.z));
            __half2 s3 = __hmul2(w00, u2h(r00.w));
            s0 = __hfma2(w01, u2h(r01.x), s0);
            s1 = __hfma2(w01, u2h(r01.y), s1);
            s2 = __hfma2(w01, u2h(r01.z), s2);
            s3 = __hfma2(w01, u2h(r01.w), s3);
            s0 = __hfma2(w10, u2h(r10.x), s0);
            s1 = __hfma2(w10, u2h(r10.y), s1);
            s2 = __hfma2(w10, u2h(r10.z), s2);
            s3 = __hfma2(w10, u2h(r10.w), s3);
            s0 = __hfma2(w11, u2h(r11.x), s0);
            s1 = __hfma2(w11, u2h(r11.y), s1);
            s2 = __hfma2(w11, u2h(r11.z), s2);
            s3 = __hfma2(w11, u2h(r11.w), s3);
            const float2 f0 = __half22float2(s0);
            const float2 f1 = __half22float2(s1);
            const float2 f2 = __half22float2(s2);
            const float2 f3 = __half22float2(s3);
            a0 += f0.x; a1 += f0.y; a2 += f1.x; a3 += f1.y;
            a4 += f2.x; a5 += f2.y; a6 += f3.x; a7 += f3.y;
        }
    }
    // Interleaved fp16 staging: channel (8c+j) -> so_h[bin*PSTRH + c + 32*j]
    __half* dst = so_h + bin * PSTRH + c;
    dst[0 * 32] = __float2half(a0 * invn);
    dst[1 * 32] = __float2half(a1 * invn);
    dst[2 * 32] = __float2half(a2 * invn);
    dst[3 * 32] = __float2half(a3 * invn);
    dst[4 * 32] = __float2half(a4 * invn);
    dst[5 * 32] = __float2half(a5 * invn);
    dst[6 * 32] = __float2half(a6 * invn);
    dst[7 * 32] = __float2half(a7 * invn);
}

template<int GH, int GW>
__device__ __forceinline__ void roi_body(
    int g, int c, const __half* __restrict__ base,
    const int* __restrict__ sxl, const int* __restrict__ sxh,
    const int* __restrict__ syl, const int* __restrict__ syh,
    const uint4* __restrict__ swq,
    __half* __restrict__ so_h)
{
    const float invn = 1.0f / (float)(GH * GW);
    const int start = 6 * g;
#pragma unroll
    for (int j = 0; j < 6; ++j) {
        process_bin<GH, GW>(start + j, c, base, invn, sxl, sxh, syl, syh, swq, so_h);
    }
    if (g == 7) {   // leftover bin 48 (warp-uniform; table-build warps excluded)
        process_bin<GH, GW>(48, c, base, invn, sxl, sxh, syl, syh, swq, so_h);
    }
}

__global__ void __launch_bounds__(256, 5)
roi_align_kernel(const float* __restrict__ boxes, float* __restrict__ out) {
    extern __shared__ __half so_h[];         // NBIN*PSTRH halfs = 25284 B
    __shared__ int   sxl[14], sxh[14], syl[14], syh[14];
    __shared__ float slx[14], shx[14], sly[14], shy[14];
    __shared__ uint4 swq[196];               // packed half2 weight quads

    const int k   = __ldg(&g_perm[blockIdx.x]);   // LPT dispatch order
    const int tid = threadIdx.x;
    const int g   = tid >> 5;      // bin group (warp)
    const int c   = tid & 31;      // channel oct

    // Phase A: per-axis sample tables with pre-scaled offsets
    if (tid < 28) {
        const float x1 = __ldg(boxes + k * 5 + 1) * 0.25f;
        const float y1 = __ldg(boxes + k * 5 + 2) * 0.25f;
        const float x2 = __ldg(boxes + k * 5 + 3) * 0.25f;
        const float y2 = __ldg(boxes + k * 5 + 4) * 0.25f;

        const bool isy = tid >= 14;
        const int  s   = isy ? tid - 14 : tid;
        const int  p   = s >> 1;
        const int  i   = s & 1;
        const float start = isy ? y1 : x1;
        const float rs    = fmaxf((isy ? y2 - y1 : x2 - x1), 1.0f);
        const float bs    = rs * (1.0f / POOLED);
        const int   gq    = (int)ceilf(rs * (1.0f / POOLED));
        const float coord = start + (float)p * bs + ((float)i + 0.5f) * bs / (float)gq;

        const bool valid = (coord >= -1.0f) && (coord <= 128.0f);
        float cc = fmaxf(coord, 0.0f);
        int lo = min((int)cc, 127);
        int hi = min(lo + 1, 127);
        float l = (lo >= 127) ? 0.0f : (cc - (float)lo);
        float h = 1.0f - l;
        if (!valid) { l = 0.0f; h = 0.0f; }   // zero both factors -> sample = 0
        if (isy) { syl[s] = lo * (WW * CC); syh[s] = hi * (WW * CC); sly[s] = l; shy[s] = h; }
        else     { sxl[s] = lo * CC;        sxh[s] = hi * CC;        slx[s] = l; shx[s] = h; }
    }
    __syncthreads();

    // Phase B: packed per-sample weight quads (lane-invariant, built once)
    if (tid < 196) {
        const int ys = tid / 14;
        const int xs = tid - ys * 14;
        const float hy = shy[ys], ly = sly[ys];
        const float hx = shx[xs], lx = slx[xs];
        uint4 q;
        q.x = h2u(__float2half2_rn(hy * hx));
        q.y = h2u(__float2half2_rn(hy * lx));
        q.z = h2u(__float2half2_rn(ly * hx));
        q.w = h2u(__float2half2_rn(ly * lx));
        swq[tid] = q;
    }
    __syncthreads();

    const int b = (int)__ldg(boxes + k * 5 + 0);
    const float roi_w = fmaxf((__ldg(boxes + k*5+3) - __ldg(boxes + k*5+1)) * 0.25f, 1.0f);
    const float roi_h = fmaxf((__ldg(boxes + k*5+4) - __ldg(boxes + k*5+2)) * 0.25f, 1.0f);
    const int gw2 = min((int)ceilf(roi_w * (1.0f / POOLED)), 2);
    const int gh2 = min((int)ceilf(roi_h * (1.0f / POOLED)), 2);

    const __half* base = g_tfeat + (size_t)b * (HWSZ * CC) + 8 * c;

    // CTA-uniform dispatch to fully-unrolled specializations
    if (gh2 == 1) {
        if (gw2 == 1) roi_body<1,1>(g, c, base, sxl, sxh, syl, syh, swq, so_h);
        else          roi_body<1,2>(g, c, base, sxl, sxh, syl, syh, swq, so_h);
    } else {
        if (gw2 == 1) roi_body<2,1>(g, c, base, sxl, sxh, syl, syh, swq, so_h);
        else          roi_body<2,2>(g, c, base, sxl, sxh, syl, syh, swq, so_h);
    }
    __syncthreads();

    // Coalesced write-out: out[k][ch][bin] = so_h[bin*PSTRH + pos(ch)]
    // pos(ch) = (ch>>3) + ((ch&7)<<5); row stride 129 words (odd) -> no conflicts
    float* dst = out + (size_t)k * PER_ROI;
#pragma unroll 7
    for (int i = tid; i < PER_ROI; i += 256) {
        const int ch  = i / NBIN;
        const int bin = i - ch * NBIN;
        const int pos = (ch >> 3) + ((ch & 7) << 5);
        dst[i] = __half2float(so_h[bin * PSTRH + pos]);
    }
}

extern "C" void kernel_launch(void* const* d_in, const int* in_sizes, int n_in,
                              void* d_out, int out_size) {
    const float* features = (const float*)d_in[0];   // [4,256,128,128]
    const float* boxes    = (const float*)d_in[1];   // [1000,5]
    float* out = (float*)d_out;                      // [1000,256,7,7]
    (void)in_sizes; (void)n_in; (void)out_size;

    const int smem_bytes = NBIN * PSTRH * (int)sizeof(__half);   // 25284

    // 1) NCHW fp32 -> NHWC fp16 scratch + LPT permutation build
    dim3 gT(WW / 32, CC / 32, BB * HH / 4);
    nchw_to_nhwc<<<gT, 256>>>(features, boxes);

    // 2) Fused gather + layout fix-up, one CTA per dispatch slot
    roi_align_kernel<<<KK, 256, smem_bytes>>>(boxes, out);
}